// round 2
// baseline (speedup 1.0000x reference)
#include <cuda_runtime.h>

#define N_NODES  100000
#define N_EDGES  3200000
#define N_GRAPHS 1024
#define NBLK_SCAN 98   // ceil(100000/1024)

// ---------------- scratch (no allocations allowed) ----------------
__device__ int    d_cnt[N_NODES];        // in-degree (excl self loop)
__device__ int    d_rowstart[N_NODES];   // CSR start per target node
__device__ int    d_cursor[N_NODES];     // fill cursors
__device__ float  d_dinv[N_NODES];       // rsqrt(deg+1)
__device__ int    d_src[N_EDGES];        // CSR source ids
__device__ float4 d_g1[N_NODES * 4];     // (x@W1)*dinv, 16 f32 = 4 float4 per node
__device__ float4 d_g2[N_NODES * 4];     // (h1@W2)*dinv
__device__ float  d_pooled[N_GRAPHS * 16];
__device__ int    d_bsum[128];
__device__ int    d_boff[128];

// ---------------- init ----------------
__global__ void zero_kernel() {
    int i = blockIdx.x * blockDim.x + threadIdx.x;
    if (i < N_NODES) d_cnt[i] = 0;
    if (i < N_GRAPHS * 16) d_pooled[i] = 0.0f;
}

// ---------------- CSR build ----------------
__global__ void hist_kernel(const int* __restrict__ col) {
    int e = blockIdx.x * blockDim.x + threadIdx.x;
    if (e < N_EDGES) {
        int c = col[e];
        atomicAdd(&d_cnt[c], 1);
    }
}

__global__ void scanA_kernel() {
    __shared__ int ws[32];
    int t = threadIdx.x;
    int i = blockIdx.x * 1024 + t;
    int v = (i < N_NODES) ? d_cnt[i] : 0;
    #pragma unroll
    for (int d = 16; d > 0; d >>= 1) v += __shfl_down_sync(0xffffffffu, v, d);
    int lane = t & 31, wid = t >> 5;
    if (lane == 0) ws[wid] = v;
    __syncthreads();
    if (wid == 0) {
        int s = ws[lane];
        #pragma unroll
        for (int d = 16; d > 0; d >>= 1) s += __shfl_down_sync(0xffffffffu, s, d);
        if (lane == 0) d_bsum[blockIdx.x] = s;
    }
}

__global__ void scanB_kernel() {
    if (threadIdx.x == 0 && blockIdx.x == 0) {
        int acc = 0;
        for (int b = 0; b < NBLK_SCAN; ++b) { d_boff[b] = acc; acc += d_bsum[b]; }
    }
}

__global__ void scanC_kernel() {
    __shared__ int ws[32];
    int t = threadIdx.x;
    int i = blockIdx.x * 1024 + t;
    int lane = t & 31, wid = t >> 5;
    int v = (i < N_NODES) ? d_cnt[i] : 0;
    // inclusive warp scan
    int x = v;
    #pragma unroll
    for (int d = 1; d < 32; d <<= 1) {
        int y = __shfl_up_sync(0xffffffffu, x, d);
        if (lane >= d) x += y;
    }
    if (lane == 31) ws[wid] = x;
    __syncthreads();
    if (wid == 0) {
        int s = ws[lane];
        #pragma unroll
        for (int d = 1; d < 32; d <<= 1) {
            int y = __shfl_up_sync(0xffffffffu, s, d);
            if (lane >= d) s += y;
        }
        ws[lane] = s;
    }
    __syncthreads();
    int excl = x - v + (wid > 0 ? ws[wid - 1] : 0);
    if (i < N_NODES) {
        int start = d_boff[blockIdx.x] + excl;
        d_rowstart[i] = start;
        d_cursor[i]   = start;
        d_dinv[i]     = rsqrtf((float)(v + 1));  // +1 self loop
    }
}

__global__ void fill_kernel(const int* __restrict__ row,
                            const int* __restrict__ col) {
    int e = blockIdx.x * blockDim.x + threadIdx.x;
    if (e < N_EDGES) {
        int c = col[e];
        int r = row[e];
        int p = atomicAdd(&d_cursor[c], 1);
        d_src[p] = r;
    }
}

// ---------------- layer 0 transform: g1 = (x @ W1) * dinv ----------------
__global__ void g1_kernel(const float* __restrict__ x,
                          const float* __restrict__ W1) {
    __shared__ float sW[48];
    int t = threadIdx.x;
    if (t < 48) sW[t] = W1[t];
    __syncthreads();
    int n = blockIdx.x * blockDim.x + t;
    if (n >= N_NODES) return;
    float x0 = x[n * 3 + 0], x1 = x[n * 3 + 1], x2 = x[n * 3 + 2];
    float dn = d_dinv[n];
    float out[16];
    #pragma unroll
    for (int f = 0; f < 16; ++f) {
        float h = x0 * sW[f] + x1 * sW[16 + f] + x2 * sW[32 + f];
        out[f] = h * dn;
    }
    float4* dst = &d_g1[n * 4];
    #pragma unroll
    for (int j = 0; j < 4; ++j)
        dst[j] = make_float4(out[4 * j], out[4 * j + 1], out[4 * j + 2], out[4 * j + 3]);
}

// ---------------- layer 1: gather + bias + ReLU + @W2 + dinv prescale ----------------
// thread = (node, chunk) with chunk = one float4 of the 16-wide feature vector.
__global__ void layer1_kernel(const float* __restrict__ b1,
                              const float* __restrict__ W2) {
    __shared__ float sW2[256];
    int t = threadIdx.x;
    sW2[t] = W2[t];  // blockDim == 256
    __syncthreads();

    int tid   = blockIdx.x * blockDim.x + t;
    int node  = tid >> 2;
    int chunk = tid & 3;
    bool valid = node < N_NODES;
    int n = valid ? node : 0;

    float4 acc = d_g1[n * 4 + chunk];  // self-loop term (g1 = h*dinv)
    int s = d_rowstart[n];
    int c = d_cnt[n];
    for (int e = s; e < s + c; ++e) {
        int src = d_src[e];
        float4 v = d_g1[src * 4 + chunk];
        acc.x += v.x; acc.y += v.y; acc.z += v.z; acc.w += v.w;
    }
    float dn = d_dinv[n];
    const float* bb = b1 + chunk * 4;
    float4 tv;
    tv.x = fmaxf(fmaf(acc.x, dn, bb[0]), 0.0f);
    tv.y = fmaxf(fmaf(acc.y, dn, bb[1]), 0.0f);
    tv.z = fmaxf(fmaf(acc.z, dn, bb[2]), 0.0f);
    tv.w = fmaxf(fmaf(acc.w, dn, bb[3]), 0.0f);

    // gather full 16-vector of this node across the 4 chunk lanes
    int lane = t & 31;
    int base = lane & ~3;
    float tt[16];
    #pragma unroll
    for (int j = 0; j < 4; ++j) {
        tt[4 * j + 0] = __shfl_sync(0xffffffffu, tv.x, base + j);
        tt[4 * j + 1] = __shfl_sync(0xffffffffu, tv.y, base + j);
        tt[4 * j + 2] = __shfl_sync(0xffffffffu, tv.z, base + j);
        tt[4 * j + 3] = __shfl_sync(0xffffffffu, tv.w, base + j);
    }

    // h2[chunk] = t @ W2 (this thread's 4 output columns)
    int c0 = chunk * 4;
    float4 h2 = make_float4(0.f, 0.f, 0.f, 0.f);
    #pragma unroll
    for (int k = 0; k < 16; ++k) {
        float tk = tt[k];
        const float* wr = &sW2[k * 16 + c0];
        h2.x = fmaf(tk, wr[0], h2.x);
        h2.y = fmaf(tk, wr[1], h2.y);
        h2.z = fmaf(tk, wr[2], h2.z);
        h2.w = fmaf(tk, wr[3], h2.w);
    }
    if (valid) {
        h2.x *= dn; h2.y *= dn; h2.z *= dn; h2.w *= dn;
        d_g2[n * 4 + chunk] = h2;
    }
}

// ---------------- layer 2: gather + bias + pool ----------------
__global__ void layer2_kernel(const float* __restrict__ b2,
                              const int* __restrict__ batch) {
    int tid   = blockIdx.x * blockDim.x + threadIdx.x;
    int node  = tid >> 2;
    int chunk = tid & 3;
    if (node >= N_NODES) return;

    float4 acc = d_g2[node * 4 + chunk];  // self loop
    int s = d_rowstart[node];
    int c = d_cnt[node];
    for (int e = s; e < s + c; ++e) {
        int src = d_src[e];
        float4 v = d_g2[src * 4 + chunk];
        acc.x += v.x; acc.y += v.y; acc.z += v.z; acc.w += v.w;
    }
    float dn = d_dinv[node];
    const float* bb = b2 + chunk * 4;
    float4 o;
    o.x = fmaf(acc.x, dn, bb[0]);
    o.y = fmaf(acc.y, dn, bb[1]);
    o.z = fmaf(acc.z, dn, bb[2]);
    o.w = fmaf(acc.w, dn, bb[3]);

    int g = batch[node];
    float* p = &d_pooled[g * 16 + chunk * 4];
    atomicAdd(p + 0, o.x);
    atomicAdd(p + 1, o.y);
    atomicAdd(p + 2, o.z);
    atomicAdd(p + 3, o.w);
}

// ---------------- head: logits + log_softmax ----------------
__global__ void head_kernel(const float* __restrict__ Wl,
                            const float* __restrict__ bl,
                            float* __restrict__ out) {
    __shared__ float sW[112];
    __shared__ float sb[7];
    int t = threadIdx.x;
    for (int i = t; i < 112; i += blockDim.x) sW[i] = Wl[i];
    if (t < 7) sb[t] = bl[t];
    __syncthreads();
    int g = blockIdx.x * blockDim.x + t;
    if (g >= N_GRAPHS) return;
    float p[16];
    #pragma unroll
    for (int k = 0; k < 16; ++k) p[k] = d_pooled[g * 16 + k];
    float l[7];
    #pragma unroll
    for (int c = 0; c < 7; ++c) {
        float acc = sb[c];
        #pragma unroll
        for (int k = 0; k < 16; ++k) acc = fmaf(p[k], sW[k * 7 + c], acc);
        l[c] = acc;
    }
    float m = l[0];
    #pragma unroll
    for (int c = 1; c < 7; ++c) m = fmaxf(m, l[c]);
    float s = 0.0f;
    #pragma unroll
    for (int c = 0; c < 7; ++c) s += expf(l[c] - m);
    float ls = logf(s);
    #pragma unroll
    for (int c = 0; c < 7; ++c) out[g * 7 + c] = l[c] - m - ls;
}

// ---------------- launch ----------------
extern "C" void kernel_launch(void* const* d_in, const int* in_sizes, int n_in,
                              void* d_out, int out_size) {
    const float* x     = (const float*)d_in[0];
    const int*   ei    = (const int*)d_in[1];
    const int*   row   = ei;
    const int*   col   = ei + N_EDGES;
    const int*   batch = (const int*)d_in[2];
    const float* W1    = (const float*)d_in[3];
    const float* b1    = (const float*)d_in[4];
    const float* W2    = (const float*)d_in[5];
    const float* b2    = (const float*)d_in[6];
    const float* Wl    = (const float*)d_in[7];
    const float* bl    = (const float*)d_in[8];
    float*       out   = (float*)d_out;

    zero_kernel<<<(N_NODES + 255) / 256, 256>>>();
    hist_kernel<<<(N_EDGES + 255) / 256, 256>>>(col);
    scanA_kernel<<<NBLK_SCAN, 1024>>>();
    scanB_kernel<<<1, 32>>>();
    scanC_kernel<<<NBLK_SCAN, 1024>>>();
    fill_kernel<<<(N_EDGES + 255) / 256, 256>>>(row, col);
    g1_kernel<<<(N_NODES + 255) / 256, 256>>>(x, W1);

    int threads2 = N_NODES * 4;
    layer1_kernel<<<(threads2 + 255) / 256, 256>>>(b1, W2);
    layer2_kernel<<<(threads2 + 255) / 256, 256>>>(b2, batch);
    head_kernel<<<(N_GRAPHS + 255) / 256, 256>>>(Wl, bl, out);
}

// round 3
// speedup vs baseline: 1.0299x; 1.0299x over previous
#include <cuda_runtime.h>

#define N_NODES  100000
#define N_EDGES  3200000
#define N_GRAPHS 1024
#define NBLK_SCAN 98   // ceil(100000/1024)

// ---------------- scratch ----------------
__device__ int    d_cnt[N_NODES];
__device__ int    d_rowstart[N_NODES];
__device__ int    d_cursor[N_NODES];
__device__ float  d_dinv[N_NODES];
__device__ int    d_src[N_EDGES];
__device__ float4 d_g1[N_NODES * 4];
__device__ float4 d_g2[N_NODES * 4];
__device__ float  d_pooled[N_GRAPHS * 16];
__device__ int    d_bsum[128];

// ---------------- init ----------------
__global__ void zero_kernel() {
    int i = blockIdx.x * blockDim.x + threadIdx.x;
    if (i < N_NODES) d_cnt[i] = 0;
    if (i < N_GRAPHS * 16) d_pooled[i] = 0.0f;
}

// ---------------- CSR build ----------------
__global__ void hist_kernel(const int4* __restrict__ col4) {
    int e = blockIdx.x * blockDim.x + threadIdx.x;   // e4 index, N_EDGES/4 of them
    if (e < N_EDGES / 4) {
        int4 c = col4[e];
        atomicAdd(&d_cnt[c.x], 1);
        atomicAdd(&d_cnt[c.y], 1);
        atomicAdd(&d_cnt[c.z], 1);
        atomicAdd(&d_cnt[c.w], 1);
    }
}

__global__ void scanA_kernel() {
    __shared__ int ws[32];
    int t = threadIdx.x;
    int i = blockIdx.x * 1024 + t;
    int v = (i < N_NODES) ? d_cnt[i] : 0;
    #pragma unroll
    for (int d = 16; d > 0; d >>= 1) v += __shfl_down_sync(0xffffffffu, v, d);
    int lane = t & 31, wid = t >> 5;
    if (lane == 0) ws[wid] = v;
    __syncthreads();
    if (wid == 0) {
        int s = ws[lane];
        #pragma unroll
        for (int d = 16; d > 0; d >>= 1) s += __shfl_down_sync(0xffffffffu, s, d);
        if (lane == 0) d_bsum[blockIdx.x] = s;
    }
}

// scanC fused: block-offset reduction (replaces scanB) + exclusive scan +
// rowstart/cursor/dinv + g1 = (x@W1)*dinv
__global__ void scanC_kernel(const float* __restrict__ x,
                             const float* __restrict__ W1) {
    __shared__ int   ws[32];
    __shared__ int   sOff;
    __shared__ float sW[48];
    int t = threadIdx.x;
    int lane = t & 31, wid = t >> 5;
    if (t < 48) sW[t] = W1[t];
    // block offset = sum d_bsum[0..bid)  (one warp, strided)
    if (wid == 0) {
        int s = 0;
        for (int b = lane; b < blockIdx.x; b += 32) s += d_bsum[b];
        #pragma unroll
        for (int d = 16; d > 0; d >>= 1) s += __shfl_down_sync(0xffffffffu, s, d);
        if (lane == 0) sOff = s;
    }
    int i = blockIdx.x * 1024 + t;
    int v = (i < N_NODES) ? d_cnt[i] : 0;
    // inclusive warp scan
    int xs = v;
    #pragma unroll
    for (int d = 1; d < 32; d <<= 1) {
        int y = __shfl_up_sync(0xffffffffu, xs, d);
        if (lane >= d) xs += y;
    }
    __syncthreads();   // protect ws reuse + ensure sOff written
    if (lane == 31) ws[wid] = xs;
    __syncthreads();
    if (wid == 0) {
        int s = ws[lane];
        #pragma unroll
        for (int d = 1; d < 32; d <<= 1) {
            int y = __shfl_up_sync(0xffffffffu, s, d);
            if (lane >= d) s += y;
        }
        ws[lane] = s;
    }
    __syncthreads();
    int excl = xs - v + (wid > 0 ? ws[wid - 1] : 0);
    if (i < N_NODES) {
        int start = sOff + excl;
        d_rowstart[i] = start;
        d_cursor[i]   = start;
        float dn = rsqrtf((float)(v + 1));
        d_dinv[i] = dn;
        // g1 = (x @ W1) * dinv
        float x0 = x[i * 3 + 0], x1 = x[i * 3 + 1], x2 = x[i * 3 + 2];
        float o[16];
        #pragma unroll
        for (int f = 0; f < 16; ++f)
            o[f] = (x0 * sW[f] + x1 * sW[16 + f] + x2 * sW[32 + f]) * dn;
        float4* dst = &d_g1[i * 4];
        #pragma unroll
        for (int j = 0; j < 4; ++j)
            dst[j] = make_float4(o[4 * j], o[4 * j + 1], o[4 * j + 2], o[4 * j + 3]);
    }
}

__global__ void fill_kernel(const int4* __restrict__ row4,
                            const int4* __restrict__ col4) {
    int e = blockIdx.x * blockDim.x + threadIdx.x;
    if (e < N_EDGES / 4) {
        int4 r = row4[e];
        int4 c = col4[e];
        d_src[atomicAdd(&d_cursor[c.x], 1)] = r.x;
        d_src[atomicAdd(&d_cursor[c.y], 1)] = r.y;
        d_src[atomicAdd(&d_cursor[c.z], 1)] = r.z;
        d_src[atomicAdd(&d_cursor[c.w], 1)] = r.w;
    }
}

// ---------------- gather helper (MLP-4 unrolled) ----------------
__device__ __forceinline__ float4 gather_sum(const float4* __restrict__ g,
                                             float4 acc, int s, int c, int chunk) {
    int e = s, end = s + c;
    for (; e + 4 <= end; e += 4) {
        int s0 = d_src[e], s1 = d_src[e + 1], s2 = d_src[e + 2], s3 = d_src[e + 3];
        float4 v0 = g[s0 * 4 + chunk];
        float4 v1 = g[s1 * 4 + chunk];
        float4 v2 = g[s2 * 4 + chunk];
        float4 v3 = g[s3 * 4 + chunk];
        acc.x += (v0.x + v1.x) + (v2.x + v3.x);
        acc.y += (v0.y + v1.y) + (v2.y + v3.y);
        acc.z += (v0.z + v1.z) + (v2.z + v3.z);
        acc.w += (v0.w + v1.w) + (v2.w + v3.w);
    }
    for (; e < end; ++e) {
        int sr = d_src[e];
        float4 v = g[sr * 4 + chunk];
        acc.x += v.x; acc.y += v.y; acc.z += v.z; acc.w += v.w;
    }
    return acc;
}

// ---------------- layer 1 ----------------
__global__ void layer1_kernel(const float* __restrict__ b1,
                              const float* __restrict__ W2) {
    __shared__ float sW2[256];
    int t = threadIdx.x;
    sW2[t] = W2[t];  // blockDim == 256
    __syncthreads();

    int tid   = blockIdx.x * blockDim.x + t;
    int node  = tid >> 2;
    int chunk = tid & 3;
    bool valid = node < N_NODES;
    int n = valid ? node : 0;

    float4 acc = d_g1[n * 4 + chunk];  // self loop
    acc = gather_sum(d_g1, acc, d_rowstart[n], d_cnt[n], chunk);

    float dn = d_dinv[n];
    const float* bb = b1 + chunk * 4;
    float4 tv;
    tv.x = fmaxf(fmaf(acc.x, dn, bb[0]), 0.0f);
    tv.y = fmaxf(fmaf(acc.y, dn, bb[1]), 0.0f);
    tv.z = fmaxf(fmaf(acc.z, dn, bb[2]), 0.0f);
    tv.w = fmaxf(fmaf(acc.w, dn, bb[3]), 0.0f);

    int lane = t & 31;
    int base = lane & ~3;
    float tt[16];
    #pragma unroll
    for (int j = 0; j < 4; ++j) {
        tt[4 * j + 0] = __shfl_sync(0xffffffffu, tv.x, base + j);
        tt[4 * j + 1] = __shfl_sync(0xffffffffu, tv.y, base + j);
        tt[4 * j + 2] = __shfl_sync(0xffffffffu, tv.z, base + j);
        tt[4 * j + 3] = __shfl_sync(0xffffffffu, tv.w, base + j);
    }

    int c0 = chunk * 4;
    float4 h2 = make_float4(0.f, 0.f, 0.f, 0.f);
    #pragma unroll
    for (int k = 0; k < 16; ++k) {
        float tk = tt[k];
        const float* wr = &sW2[k * 16 + c0];
        h2.x = fmaf(tk, wr[0], h2.x);
        h2.y = fmaf(tk, wr[1], h2.y);
        h2.z = fmaf(tk, wr[2], h2.z);
        h2.w = fmaf(tk, wr[3], h2.w);
    }
    if (valid) {
        h2.x *= dn; h2.y *= dn; h2.z *= dn; h2.w *= dn;
        d_g2[n * 4 + chunk] = h2;
    }
}

// ---------------- layer 2 + pool ----------------
__global__ void layer2_kernel(const float* __restrict__ b2,
                              const int* __restrict__ batch) {
    int tid   = blockIdx.x * blockDim.x + threadIdx.x;
    int node  = tid >> 2;
    int chunk = tid & 3;
    if (node >= N_NODES) return;

    float4 acc = d_g2[node * 4 + chunk];  // self loop
    acc = gather_sum(d_g2, acc, d_rowstart[node], d_cnt[node], chunk);

    float dn = d_dinv[node];
    const float* bb = b2 + chunk * 4;
    float4 o;
    o.x = fmaf(acc.x, dn, bb[0]);
    o.y = fmaf(acc.y, dn, bb[1]);
    o.z = fmaf(acc.z, dn, bb[2]);
    o.w = fmaf(acc.w, dn, bb[3]);

    int g = batch[node];
    float* p = &d_pooled[g * 16 + chunk * 4];
    atomicAdd(p + 0, o.x);
    atomicAdd(p + 1, o.y);
    atomicAdd(p + 2, o.z);
    atomicAdd(p + 3, o.w);
}

// ---------------- head ----------------
__global__ void head_kernel(const float* __restrict__ Wl,
                            const float* __restrict__ bl,
                            float* __restrict__ out) {
    __shared__ float sW[112];
    __shared__ float sb[7];
    int t = threadIdx.x;
    for (int i = t; i < 112; i += blockDim.x) sW[i] = Wl[i];
    if (t < 7) sb[t] = bl[t];
    __syncthreads();
    int g = blockIdx.x * blockDim.x + t;
    if (g >= N_GRAPHS) return;
    float p[16];
    #pragma unroll
    for (int k = 0; k < 16; ++k) p[k] = d_pooled[g * 16 + k];
    float l[7];
    #pragma unroll
    for (int c = 0; c < 7; ++c) {
        float acc = sb[c];
        #pragma unroll
        for (int k = 0; k < 16; ++k) acc = fmaf(p[k], sW[k * 7 + c], acc);
        l[c] = acc;
    }
    float m = l[0];
    #pragma unroll
    for (int c = 1; c < 7; ++c) m = fmaxf(m, l[c]);
    float s = 0.0f;
    #pragma unroll
    for (int c = 0; c < 7; ++c) s += expf(l[c] - m);
    float ls = logf(s);
    #pragma unroll
    for (int c = 0; c < 7; ++c) out[g * 7 + c] = l[c] - m - ls;
}

// ---------------- launch ----------------
extern "C" void kernel_launch(void* const* d_in, const int* in_sizes, int n_in,
                              void* d_out, int out_size) {
    const float* x     = (const float*)d_in[0];
    const int*   ei    = (const int*)d_in[1];
    const int*   row   = ei;
    const int*   col   = ei + N_EDGES;
    const int*   batch = (const int*)d_in[2];
    const float* W1    = (const float*)d_in[3];
    const float* b1    = (const float*)d_in[4];
    const float* W2    = (const float*)d_in[6 - 2];  // d_in[4]=b1, d_in[5]=W2
    const float* b2    = (const float*)d_in[6];
    const float* Wl    = (const float*)d_in[7];
    const float* bl    = (const float*)d_in[8];
    float*       out   = (float*)d_out;
    W2 = (const float*)d_in[5];

    zero_kernel<<<(N_NODES + 255) / 256, 256>>>();
    hist_kernel<<<(N_EDGES / 4 + 255) / 256, 256>>>((const int4*)col);
    scanA_kernel<<<NBLK_SCAN, 1024>>>();
    scanC_kernel<<<NBLK_SCAN, 1024>>>(x, W1);
    fill_kernel<<<(N_EDGES / 4 + 255) / 256, 256>>>((const int4*)row, (const int4*)col);

    int threads2 = N_NODES * 4;
    layer1_kernel<<<(threads2 + 255) / 256, 256>>>(b1, W2);
    layer2_kernel<<<(threads2 + 255) / 256, 256>>>(b2, batch);
    head_kernel<<<(N_GRAPHS + 255) / 256, 256>>>(Wl, bl, out);
}

// round 4
// speedup vs baseline: 1.0640x; 1.0331x over previous
#include <cuda_runtime.h>
#include <cuda_fp16.h>

#define N_NODES  100000
#define N_EDGES  3200000
#define N_GRAPHS 1024
#define SCAN_BLK 256
#define NBLK_SCAN ((N_NODES + SCAN_BLK - 1) / SCAN_BLK)   // 391

// 8-byte feature chunk: 4 fp16 values
struct __align__(8) H4 { __half2 a, b; };

// ---------------- scratch ----------------
__device__ int    d_cnt[N_NODES];
__device__ int    d_rowstart[N_NODES];
__device__ int    d_cursor[N_NODES];
__device__ float  d_dinv[N_NODES];
__device__ int    d_src[N_EDGES];
__device__ H4     d_g1h[N_NODES * 4];
__device__ H4     d_g2h[N_NODES * 4];
__device__ float  d_pooled[N_GRAPHS * 16];
__device__ int    d_bsum[NBLK_SCAN + 1];

// ---------------- init ----------------
__global__ void zero_kernel() {
    int i = blockIdx.x * blockDim.x + threadIdx.x;
    if (i < N_NODES) d_cnt[i] = 0;
    if (i < N_GRAPHS * 16) d_pooled[i] = 0.0f;
}

// ---------------- CSR build ----------------
__global__ void hist_kernel(const int4* __restrict__ col4) {
    int e = blockIdx.x * blockDim.x + threadIdx.x;
    if (e < N_EDGES / 4) {
        int4 c = col4[e];
        atomicAdd(&d_cnt[c.x], 1);
        atomicAdd(&d_cnt[c.y], 1);
        atomicAdd(&d_cnt[c.z], 1);
        atomicAdd(&d_cnt[c.w], 1);
    }
}

__global__ void scanA_kernel() {
    __shared__ int ws[SCAN_BLK / 32];
    int t = threadIdx.x;
    int i = blockIdx.x * SCAN_BLK + t;
    int v = (i < N_NODES) ? d_cnt[i] : 0;
    #pragma unroll
    for (int d = 16; d > 0; d >>= 1) v += __shfl_down_sync(0xffffffffu, v, d);
    int lane = t & 31, wid = t >> 5;
    if (lane == 0) ws[wid] = v;
    __syncthreads();
    if (wid == 0 && lane == 0) {
        int s = 0;
        #pragma unroll
        for (int w = 0; w < SCAN_BLK / 32; ++w) s += ws[w];
        d_bsum[blockIdx.x] = s;
    }
}

// scanC fused: block-offset pre-sum + exclusive scan + rowstart/cursor/dinv +
// g1 = (x@W1)*dinv stored as fp16
__global__ void scanC_kernel(const float* __restrict__ x,
                             const float* __restrict__ W1) {
    const int NW = SCAN_BLK / 32;
    __shared__ int   ws[NW];
    __shared__ int   sOff;
    __shared__ float sW[48];
    int t = threadIdx.x;
    int lane = t & 31, wid = t >> 5;
    if (t < 48) sW[t] = W1[t];
    // block offset = sum d_bsum[0..bid)
    if (wid == 0) {
        int s = 0;
        for (int b = lane; b < blockIdx.x; b += 32) s += d_bsum[b];
        #pragma unroll
        for (int d = 16; d > 0; d >>= 1) s += __shfl_down_sync(0xffffffffu, s, d);
        if (lane == 0) sOff = s;
    }
    int i = blockIdx.x * SCAN_BLK + t;
    int v = (i < N_NODES) ? d_cnt[i] : 0;
    // inclusive warp scan
    int xs = v;
    #pragma unroll
    for (int d = 1; d < 32; d <<= 1) {
        int y = __shfl_up_sync(0xffffffffu, xs, d);
        if (lane >= d) xs += y;
    }
    if (lane == 31) ws[wid] = xs;
    __syncthreads();
    if (wid == 0) {
        int s = (lane < NW) ? ws[lane] : 0;
        #pragma unroll
        for (int d = 1; d < NW; d <<= 1) {
            int y = __shfl_up_sync(0xffffffffu, s, d);
            if (lane >= d) s += y;
        }
        if (lane < NW) ws[lane] = s;
    }
    __syncthreads();
    int excl = xs - v + (wid > 0 ? ws[wid - 1] : 0);
    if (i < N_NODES) {
        int start = sOff + excl;
        d_rowstart[i] = start;
        d_cursor[i]   = start;
        float dn = rsqrtf((float)(v + 1));
        d_dinv[i] = dn;
        float x0 = x[i * 3 + 0], x1 = x[i * 3 + 1], x2 = x[i * 3 + 2];
        float o[16];
        #pragma unroll
        for (int f = 0; f < 16; ++f)
            o[f] = (x0 * sW[f] + x1 * sW[16 + f] + x2 * sW[32 + f]) * dn;
        #pragma unroll
        for (int j = 0; j < 4; ++j) {
            H4 h;
            h.a = __floats2half2_rn(o[4 * j + 0], o[4 * j + 1]);
            h.b = __floats2half2_rn(o[4 * j + 2], o[4 * j + 3]);
            d_g1h[i * 4 + j] = h;
        }
    }
}

__global__ void fill_kernel(const int4* __restrict__ row4,
                            const int4* __restrict__ col4) {
    int e = blockIdx.x * blockDim.x + threadIdx.x;
    if (e < N_EDGES / 4) {
        int4 r = row4[e];
        int4 c = col4[e];
        d_src[atomicAdd(&d_cursor[c.x], 1)] = r.x;
        d_src[atomicAdd(&d_cursor[c.y], 1)] = r.y;
        d_src[atomicAdd(&d_cursor[c.z], 1)] = r.z;
        d_src[atomicAdd(&d_cursor[c.w], 1)] = r.w;
    }
}

// ---------------- gather helper (fp16 storage, fp32 accumulate, MLP-4) ----------------
__device__ __forceinline__ void acc_h4(float4& acc, H4 v) {
    float2 fa = __half22float2(v.a);
    float2 fb = __half22float2(v.b);
    acc.x += fa.x; acc.y += fa.y; acc.z += fb.x; acc.w += fb.y;
}

__device__ __forceinline__ float4 gather_sum(const H4* __restrict__ g,
                                             float4 acc, int s, int c, int chunk) {
    int e = s, end = s + c;
    for (; e + 4 <= end; e += 4) {
        int s0 = d_src[e], s1 = d_src[e + 1], s2 = d_src[e + 2], s3 = d_src[e + 3];
        H4 v0 = g[s0 * 4 + chunk];
        H4 v1 = g[s1 * 4 + chunk];
        H4 v2 = g[s2 * 4 + chunk];
        H4 v3 = g[s3 * 4 + chunk];
        acc_h4(acc, v0); acc_h4(acc, v1); acc_h4(acc, v2); acc_h4(acc, v3);
    }
    for (; e < end; ++e) {
        H4 v = g[d_src[e] * 4 + chunk];
        acc_h4(acc, v);
    }
    return acc;
}

// ---------------- layer 1 ----------------
__global__ void layer1_kernel(const float* __restrict__ b1,
                              const float* __restrict__ W2) {
    __shared__ float sW2[256];
    int t = threadIdx.x;
    sW2[t] = W2[t];  // blockDim == 256
    __syncthreads();

    int tid   = blockIdx.x * blockDim.x + t;
    int node  = tid >> 2;
    int chunk = tid & 3;
    bool valid = node < N_NODES;
    int n = valid ? node : 0;

    float4 acc = make_float4(0.f, 0.f, 0.f, 0.f);
    acc_h4(acc, d_g1h[n * 4 + chunk]);  // self loop
    acc = gather_sum(d_g1h, acc, d_rowstart[n], d_cnt[n], chunk);

    float dn = d_dinv[n];
    const float* bb = b1 + chunk * 4;
    float4 tv;
    tv.x = fmaxf(fmaf(acc.x, dn, bb[0]), 0.0f);
    tv.y = fmaxf(fmaf(acc.y, dn, bb[1]), 0.0f);
    tv.z = fmaxf(fmaf(acc.z, dn, bb[2]), 0.0f);
    tv.w = fmaxf(fmaf(acc.w, dn, bb[3]), 0.0f);

    int lane = t & 31;
    int base = lane & ~3;
    float tt[16];
    #pragma unroll
    for (int j = 0; j < 4; ++j) {
        tt[4 * j + 0] = __shfl_sync(0xffffffffu, tv.x, base + j);
        tt[4 * j + 1] = __shfl_sync(0xffffffffu, tv.y, base + j);
        tt[4 * j + 2] = __shfl_sync(0xffffffffu, tv.z, base + j);
        tt[4 * j + 3] = __shfl_sync(0xffffffffu, tv.w, base + j);
    }

    int c0 = chunk * 4;
    float4 h2 = make_float4(0.f, 0.f, 0.f, 0.f);
    #pragma unroll
    for (int k = 0; k < 16; ++k) {
        float tk = tt[k];
        const float* wr = &sW2[k * 16 + c0];
        h2.x = fmaf(tk, wr[0], h2.x);
        h2.y = fmaf(tk, wr[1], h2.y);
        h2.z = fmaf(tk, wr[2], h2.z);
        h2.w = fmaf(tk, wr[3], h2.w);
    }
    if (valid) {
        H4 hv;
        hv.a = __floats2half2_rn(h2.x * dn, h2.y * dn);
        hv.b = __floats2half2_rn(h2.z * dn, h2.w * dn);
        d_g2h[n * 4 + chunk] = hv;
    }
}

// ---------------- layer 2 + pool ----------------
__global__ void layer2_kernel(const float* __restrict__ b2,
                              const int* __restrict__ batch) {
    int tid   = blockIdx.x * blockDim.x + threadIdx.x;
    int node  = tid >> 2;
    int chunk = tid & 3;
    if (node >= N_NODES) return;

    float4 acc = make_float4(0.f, 0.f, 0.f, 0.f);
    acc_h4(acc, d_g2h[node * 4 + chunk]);  // self loop
    acc = gather_sum(d_g2h, acc, d_rowstart[node], d_cnt[node], chunk);

    float dn = d_dinv[node];
    const float* bb = b2 + chunk * 4;
    float4 o;
    o.x = fmaf(acc.x, dn, bb[0]);
    o.y = fmaf(acc.y, dn, bb[1]);
    o.z = fmaf(acc.z, dn, bb[2]);
    o.w = fmaf(acc.w, dn, bb[3]);

    int g = batch[node];
    float* p = &d_pooled[g * 16 + chunk * 4];
    atomicAdd(p + 0, o.x);
    atomicAdd(p + 1, o.y);
    atomicAdd(p + 2, o.z);
    atomicAdd(p + 3, o.w);
}

// ---------------- head ----------------
__global__ void head_kernel(const float* __restrict__ Wl,
                            const float* __restrict__ bl,
                            float* __restrict__ out) {
    __shared__ float sW[112];
    __shared__ float sb[7];
    int t = threadIdx.x;
    for (int i = t; i < 112; i += blockDim.x) sW[i] = Wl[i];
    if (t < 7) sb[t] = bl[t];
    __syncthreads();
    int g = blockIdx.x * blockDim.x + t;
    if (g >= N_GRAPHS) return;
    float p[16];
    #pragma unroll
    for (int k = 0; k < 16; ++k) p[k] = d_pooled[g * 16 + k];
    float l[7];
    #pragma unroll
    for (int c = 0; c < 7; ++c) {
        float acc = sb[c];
        #pragma unroll
        for (int k = 0; k < 16; ++k) acc = fmaf(p[k], sW[k * 7 + c], acc);
        l[c] = acc;
    }
    float m = l[0];
    #pragma unroll
    for (int c = 1; c < 7; ++c) m = fmaxf(m, l[c]);
    float s = 0.0f;
    #pragma unroll
    for (int c = 0; c < 7; ++c) s += expf(l[c] - m);
    float ls = logf(s);
    #pragma unroll
    for (int c = 0; c < 7; ++c) out[g * 7 + c] = l[c] - m - ls;
}

// ---------------- launch ----------------
extern "C" void kernel_launch(void* const* d_in, const int* in_sizes, int n_in,
                              void* d_out, int out_size) {
    const float* x     = (const float*)d_in[0];
    const int*   ei    = (const int*)d_in[1];
    const int*   row   = ei;
    const int*   col   = ei + N_EDGES;
    const int*   batch = (const int*)d_in[2];
    const float* W1    = (const float*)d_in[3];
    const float* b1    = (const float*)d_in[4];
    const float* W2    = (const float*)d_in[5];
    const float* b2    = (const float*)d_in[6];
    const float* Wl    = (const float*)d_in[7];
    const float* bl    = (const float*)d_in[8];
    float*       out   = (float*)d_out;

    zero_kernel<<<(N_NODES + 255) / 256, 256>>>();
    hist_kernel<<<(N_EDGES / 4 + 255) / 256, 256>>>((const int4*)col);
    scanA_kernel<<<NBLK_SCAN, SCAN_BLK>>>();
    scanC_kernel<<<NBLK_SCAN, SCAN_BLK>>>(x, W1);
    fill_kernel<<<(N_EDGES / 4 + 255) / 256, 256>>>((const int4*)row, (const int4*)col);

    int threads2 = N_NODES * 4;
    layer1_kernel<<<(threads2 + 255) / 256, 256>>>(b1, W2);
    layer2_kernel<<<(threads2 + 255) / 256, 256>>>(b2, batch);
    head_kernel<<<(N_GRAPHS + 255) / 256, 256>>>(Wl, bl, out);
}